// round 14
// baseline (speedup 1.0000x reference)
#include <cuda_runtime.h>
#include <cstdint>
#include <math.h>

#define NT    1024
#define NPIX  (8*4*1024*1024)
#define NCELL 512         // 65536-wide d-cells; min bin width 104858 > 65536
#define WLO   80          // fine window covers k in [81, 144]
#define WNB   64

// ---- static device scratch ----
__device__ int g_B[NT];              // integer boundaries: M > B[k] <=> fp32(M*c) > T[k]
__device__ unsigned g_plut[NCELL];   // packed per-cell: (t<<9)|kb ; k = kb + ((d&0xFFFF)>=t)
__device__ int g_cnt80;              // count(M > B[80])
__device__ int g_fine[WNB];          // fine histogram: count(u == 81+j)
__device__ unsigned g_bin[NPIX/4];   // per-pixel exact ladder index (sat 255), 4x u8

__device__ __forceinline__ double wscale() {
  const float W = (float)(1.0 / 25.0);
  return (double)W / 8388608.0;
}

// ---------------------------------------------------------------------------
// K0a: exact integer boundaries, parallel over 8 blocks (fp64 is per-SM slow).
// ---------------------------------------------------------------------------
__global__ void __launch_bounds__(128) k_bound() {
  const int k = blockIdx.x * 128 + threadIdx.x;   // grid 8 x 128 = 1024
  if (blockIdx.x == 0) {
    if (threadIdx.x == 0) g_cnt80 = 0;
    if (threadIdx.x < WNB) g_fine[threadIdx.x] = 0;
  }
  float T = 0.5f;                                  // exact fp32 ladder replay
  for (int i = 0; i < k; ++i) T = T - 0.0005f;
  const double c = wscale();
  double dM = (double)T / c;
  long long Mg = (long long)floor(dM);
  if (Mg < -1) Mg = -1;
  if (Mg > 400000000LL) Mg = 400000000LL;
  while ((float)((double)(Mg + 1) * c) <= T) Mg++;
  while (Mg >= 0 && (float)((double)Mg * c) > T) Mg--;
  g_B[k] = (int)Mg;
}

// ---------------------------------------------------------------------------
// K0b: packed LUT, 512 cells of width 65536 in d = B0 - M.
// kb = smallest k with (top-of-cell M) > B[k], saturated to 255.
// t  = offset of the k=kb boundary inside the cell (clamped to 65536 = never).
// ---------------------------------------------------------------------------
__global__ void __launch_bounds__(512) k_plut() {
  __shared__ int Bsh[NT];
  const int t = threadIdx.x;
  Bsh[t] = g_B[t];
  Bsh[t + 512] = g_B[t + 512];
  __syncthreads();
  const int B0 = Bsh[0];
  const int i = t;                               // cell index
  const long long Mh = (long long)B0 - ((long long)i << 16);  // largest M in cell
  int lo = 1, hi = 1023, res = 1024;             // smallest k with Mh > B[k]
  while (lo <= hi) {
    int mid = (lo + hi) >> 1;
    if (Mh > (long long)Bsh[mid]) { res = mid; hi = mid - 1; }
    else lo = mid + 1;
  }
  unsigned kb, tt;
  if (res > 255) { kb = 255u; tt = 65536u; }     // saturated: never corrected
  else {
    kb = (unsigned)res;
    long long dkb = (long long)B0 - (long long)Bsh[res] - ((long long)i << 16);
    tt = (dkb > 65536) ? 65536u : (unsigned)dkb; // >= 1 by construction
  }
  g_plut[i] = (tt << 9) | kb;
}

// ---------------------------------------------------------------------------
// K1: exact integer 5x5 box blur (running sums) + single-LDS packed-LUT index,
//     u8 store, register cnt80, fused per-warp fine histogram.
//     8 warps = 8 x 128-col strips; 32-row band. Grid 1024.
// ---------------------------------------------------------------------------
__global__ void __launch_bounds__(256) k_blur(const float* __restrict__ x) {
  __shared__ unsigned lutsh[NCELL];      // 2KB packed LUT
  __shared__ int fh[8][WNB];             // per-warp privatized fine histogram
  const int tid = threadIdx.x, lane = tid & 31, w = tid >> 5;
  if (tid < NCELL / 4) ((uint4*)lutsh)[tid] = ((const uint4*)g_plut)[tid];
  if (lane < 32) { fh[w][lane] = 0; fh[w][lane + 32] = 0; }
  const int B0 = g_B[0];
  __syncthreads();

  const int ch = blockIdx.x >> 5;
  const int y0 = (blockIdx.x & 31) << 5;
  const float4* xo = (const float4*)x + ((size_t)ch << 18);
  const float*  xs = x + ((size_t)ch << 20);
  unsigned* bp = g_bin + ((size_t)ch << 18);

  const int c0 = (w << 7) + (lane << 2);
  const int hcol = (lane == 0) ? (c0 - 2) : (c0 + 4);
  const bool hval = (lane == 0) ? (w > 0) : ((lane == 31) && (w < 7));
  int cnt80 = 0;

  auto ldOwn = [&](int y) -> int4 {
    int4 m = make_int4(0, 0, 0, 0);
    if ((unsigned)y < 1024u) {
      float4 v = __ldg(xo + ((size_t)y << 8) + tid);
      m.x = (int)(v.x * 8388608.0f);
      m.y = (int)(v.y * 8388608.0f);
      m.z = (int)(v.z * 8388608.0f);
      m.w = (int)(v.w * 8388608.0f);
    }
    return m;
  };
  auto ldHalo = [&](int y) -> int2 {
    int2 m = make_int2(0, 0);
    if (hval && (unsigned)y < 1024u) {
      float2 v = __ldg((const float2*)(xs + ((size_t)y << 10) + hcol));
      m.x = (int)(v.x * 8388608.0f);
      m.y = (int)(v.y * 8388608.0f);
    }
    return m;
  };
  // exact saturated ladder index: ONE LDS.32, branchless
  auto uidx = [&](int M) -> int {
    const int d = B0 - M;
    int dc = d < 0 ? 0 : d;
    unsigned idx = (unsigned)dc >> 16;
    if (idx > NCELL - 1) idx = NCELL - 1;
    const unsigned e = lutsh[idx];
    int k = (int)(e & 0x1FFu) + (int)(((unsigned)dc & 0xFFFFu) >= (e >> 9));
    if (k > 255) k = 255;
    return d < 0 ? 0 : k;
  };
  auto tally = [&](int u) {
    cnt80 += (u <= WLO);
    unsigned tb = (unsigned)(u - (WLO + 1));
    if (tb < (unsigned)WNB) atomicAdd(&fh[w][tb], 1);
  };

  int4 r0 = ldOwn(y0 - 2), r1 = ldOwn(y0 - 1), r2 = ldOwn(y0), r3 = ldOwn(y0 + 1);
  int2 h0 = ldHalo(y0 - 2), h1 = ldHalo(y0 - 1), h2 = ldHalo(y0), h3 = ldHalo(y0 + 1);
  int4 S;
  S.x = r0.x + r1.x + r2.x + r3.x;
  S.y = r0.y + r1.y + r2.y + r3.y;
  S.z = r0.z + r1.z + r2.z + r3.z;
  S.w = r0.w + r1.w + r2.w + r3.w;
  int2 Sh = make_int2(h0.x + h1.x + h2.x + h3.x, h0.y + h1.y + h2.y + h3.y);

  for (int yy = 0; yy < 32; ++yy) {
    const int y = y0 + yy;
    int4 nw = ldOwn(y + 2);
    int2 nh = ldHalo(y + 2);
    S.x += nw.x; S.y += nw.y; S.z += nw.z; S.w += nw.w;
    Sh.x += nh.x; Sh.y += nh.y;

    int l2 = __shfl_up_sync(0xFFFFFFFFu, S.z, 1);
    int l1 = __shfl_up_sync(0xFFFFFFFFu, S.w, 1);
    int q1 = __shfl_down_sync(0xFFFFFFFFu, S.x, 1);
    int q2 = __shfl_down_sync(0xFFFFFFFFu, S.y, 1);
    if (lane == 0)  { l2 = Sh.x; l1 = Sh.y; }
    if (lane == 31) { q1 = Sh.x; q2 = Sh.y; }

    const int Mx = l2 + l1 + S.x + S.y + S.z;
    const int My = Mx - l2 + S.w;
    const int Mz = My - l1 + q1;
    const int Mw = Mz - S.x + q2;

    const int u0 = uidx(Mx), u1 = uidx(My), u2 = uidx(Mz), u3 = uidx(Mw);
    bp[((size_t)y << 8) + tid] =
        (unsigned)u0 | ((unsigned)u1 << 8) | ((unsigned)u2 << 16) | ((unsigned)u3 << 24);
    tally(u0); tally(u1); tally(u2); tally(u3);

    S.x -= r0.x; S.y -= r0.y; S.z -= r0.z; S.w -= r0.w;
    Sh.x -= h0.x; Sh.y -= h0.y;
    r0 = r1; r1 = r2; r2 = r3; r3 = nw;
    h0 = h1; h1 = h2; h2 = h3; h3 = nh;
  }

  cnt80 += __shfl_down_sync(0xFFFFFFFFu, cnt80, 16);
  cnt80 += __shfl_down_sync(0xFFFFFFFFu, cnt80, 8);
  cnt80 += __shfl_down_sync(0xFFFFFFFFu, cnt80, 4);
  cnt80 += __shfl_down_sync(0xFFFFFFFFu, cnt80, 2);
  cnt80 += __shfl_down_sync(0xFFFFFFFFu, cnt80, 1);
  if (lane == 0) atomicAdd(&g_cnt80, cnt80);

  __syncthreads();
  if (tid < WNB) {
    int s = fh[0][tid] + fh[1][tid] + fh[2][tid] + fh[3][tid]
          + fh[4][tid] + fh[5][tid] + fh[6][tid] + fh[7][tid];
    if (s) atomicAdd(&g_fine[tid], s);
  }
}

// ---------------------------------------------------------------------------
// K2: fused pick (staged parallel loads) + threshold + bitwise close + expand.
// 1024x32 tiles, grid 1024.  (R13 config, frozen.)
// ---------------------------------------------------------------------------
__global__ void __launch_bounds__(256) k_morph(float* __restrict__ out) {
  __shared__ unsigned bits[40][33];
  __shared__ unsigned hd[40][33];
  __shared__ unsigned dv[36][33];
  __shared__ unsigned he[36][33];
  __shared__ unsigned ve[32][33];
  __shared__ uint4 lut16[16];
  __shared__ int sf[WNB];
  __shared__ int c80_s, a_s;
  const int tid  = threadIdx.x;
  const int lane = tid & 31;
  const int wid  = tid >> 5;
  const int ch = blockIdx.x >> 5;
  const int y0 = (blockIdx.x & 31) << 5;
  const unsigned* bw = g_bin + ((size_t)ch << 18);

  if (tid < WNB) sf[tid] = g_fine[tid];
  if (tid == WNB) c80_s = g_cnt80;
  if (tid < 16)
    lut16[tid] = make_uint4((tid & 1) ? 0x3f800000u : 0u,
                            (tid & 2) ? 0x3f800000u : 0u,
                            (tid & 4) ? 0x3f800000u : 0u,
                            (tid & 8) ? 0x3f800000u : 0u);
  __syncthreads();
  if (tid == 0) {
    const float invN = 1.0f / 33554432.0f;    // N = 2^25
    int flag = 0, a = 0;
    int C = c80_s;                            // cum count at k = 80
    if ((float)C * invN >= 0.84f) flag = 1;
    else {
      int k = -1;
      for (int j = 0; j < WNB; ++j) {
        C += sf[j];
        if ((float)C * invN >= 0.84f) { k = WLO + 1 + j; break; }
      }
      if (k < 0) flag = 1;
      else {
        while ((float)C * invN > 0.86f) {     // statistically never iterates
          if (k <= WLO) { flag = 1; break; }
          C -= sf[k - (WLO + 1)];
          k--;
        }
        a = k;
      }
    }
    if (flag) {
      // fallback (never taken): exact serial recount from stored u8 bins
      int h[256];
      for (int i = 0; i < 256; ++i) h[i] = 0;
      const unsigned char* p = (const unsigned char*)g_bin;
      for (long long i = 0; i < (long long)NPIX; ++i) h[p[i]]++;
      int C2 = 0, k = 254;
      for (int j = 0; j <= 254; ++j) {
        C2 += h[j];
        if ((float)C2 * invN >= 0.84f) { k = j; break; }
      }
      while (k > 0 && (float)C2 * invN > 0.86f) { C2 -= h[k]; k--; }
      a = k;
    }
    a_s = a;
  }
  __syncthreads();
  const int a = a_s;
  const unsigned C7 = (unsigned)(127 - (a & 127)) * 0x01010101u;
  const bool alow = a < 128;

  auto nib = [&](unsigned pk) -> unsigned {
    const unsigned hi = pk & 0x80808080u;
    const unsigned m  = ((pk & 0x7F7F7F7Fu) + C7) & 0x80808080u;
    const unsigned gt = alow ? (hi | m) : (hi & m);
    const unsigned vb = ((~gt) >> 7) & 0x01010101u;
    return (vb * 0x01020408u) >> 24;
  };

  // phase 1: threshold bitmasks; lane loads 16 px (uint4), pairs via 1 shfl
  {
    const uint4* bw4 = (const uint4*)bw;
    for (int t = wid; t < 80; t += 8) {
      const int r = t >> 1, h = t & 1;
      const int gy = y0 - 4 + r;
      unsigned v = 0;
      if ((unsigned)gy < 1024u) {
        const uint4 p4 = __ldg(&bw4[((size_t)gy << 6) + (h << 5) + lane]);
        const unsigned b16 = nib(p4.x) | (nib(p4.y) << 4)
                           | (nib(p4.z) << 8) | (nib(p4.w) << 12);
        v = b16 << ((lane & 1) << 4);
      }
      v |= __shfl_xor_sync(0xFFFFFFFFu, v, 1);
      if ((lane & 1) == 0) bits[r][(h << 4) + (lane >> 1)] = v;
    }
  }
  __syncthreads();

  // phase 2: horizontal dilate (0-fill)
  for (int idx = tid; idx < 40 * 32; idx += 256) {
    const int r = idx >> 5, w = idx & 31;
    const unsigned u = bits[r][w];
    const unsigned L = w ? bits[r][w - 1] : 0u;
    const unsigned R = (w < 31) ? bits[r][w + 1] : 0u;
    hd[r][w] = u | __funnelshift_r(u, R, 1) | __funnelshift_r(u, R, 2)
                 | __funnelshift_l(L, u, 1) | __funnelshift_l(L, u, 2);
  }
  __syncthreads();

  // phase 3: vertical dilate, sliding 5-tap window
  {
    const int w = tid & 31, g = tid >> 5;
    const int r0 = g * 5;
    if (r0 < 36) {
      const int rend = (r0 + 5 < 36) ? (r0 + 5) : 36;
      unsigned w0 = hd[r0][w],     w1 = hd[r0 + 1][w];
      unsigned w2 = hd[r0 + 2][w], w3 = hd[r0 + 3][w];
      for (int r = r0; r < rend; ++r) {
        const unsigned w4 = hd[r + 4][w];
        dv[r][w] = w0 | w1 | w2 | w3 | w4;
        w0 = w1; w1 = w2; w2 = w3; w3 = w4;
      }
    }
  }
  __syncthreads();

  // phase 4: horizontal erode (1-fill); out-of-image rows forced to all-ones
  for (int idx = tid; idx < 36 * 32; idx += 256) {
    const int r = idx >> 5, w = idx & 31;
    const unsigned u = dv[r][w];
    const unsigned L = w ? dv[r][w - 1] : 0xFFFFFFFFu;
    const unsigned R = (w < 31) ? dv[r][w + 1] : 0xFFFFFFFFu;
    unsigned res = u & __funnelshift_r(u, R, 1) & __funnelshift_r(u, R, 2)
                     & __funnelshift_l(L, u, 1) & __funnelshift_l(L, u, 2);
    if ((y0 == 0 && r < 2) || (y0 == 992 && r >= 34)) res = 0xFFFFFFFFu;
    he[r][w] = res;
  }
  __syncthreads();

  // phase 5a: vertical erode, sliding 5-tap window (clip-free)
  {
    const int w = tid & 31, g = tid >> 5;
    const int r0 = g << 2;
    unsigned w0 = he[r0][w],     w1 = he[r0 + 1][w];
    unsigned w2 = he[r0 + 2][w], w3 = he[r0 + 3][w];
#pragma unroll
    for (int i = 0; i < 4; ++i) {
      const unsigned w4 = he[r0 + 4 + i][w];
      ve[r0 + i][w] = w0 & w1 & w2 & w3 & w4;
      w0 = w1; w1 = w2; w2 = w3; w3 = w4;
    }
  }
  __syncthreads();

  // phase 5b: LUT16 expand + coalesced uint4 stores
  uint4* op = (uint4*)out + ((size_t)ch << 18);
  for (int task = wid; task < 32 * 8; task += 8) {
    const int yy = task >> 3, seg = task & 7;
    const int gy = y0 + yy;
    const unsigned o = ve[yy][(seg << 2) + (lane >> 3)];
    op[((size_t)gy << 8) + (seg << 5) + lane] = lut16[(o >> ((lane & 7) << 2)) & 15u];
  }
}

// ---------------------------------------------------------------------------
extern "C" void kernel_launch(void* const* d_in, const int* in_sizes, int n_in,
                              void* d_out, int out_size) {
  const float* x = (const float*)d_in[0];
  if (n_in > 1 && in_sizes[0] < in_sizes[1]) x = (const float*)d_in[1];

  k_bound<<<8,    128 >>>();
  k_plut <<<1,    512 >>>();
  k_blur <<<1024, 256 >>>(x);
  k_morph<<<1024, 256 >>>((float*)d_out);
}

// round 15
// speedup vs baseline: 1.0352x; 1.0352x over previous
#include <cuda_runtime.h>
#include <cstdint>
#include <math.h>

#define NT    1024
#define NPIX  (8*4*1024*1024)
#define NCELL 8192
#define WLO   80          // fine window covers k in [81, 144]
#define WNB   64

// ---- static device scratch ----
__device__ int g_B[NT];                  // integer boundaries: M > B[k] <=> fp32(M*c) > T[k]
__device__ __align__(16) unsigned char g_lut[NCELL];
__device__ int g_cnt80;                  // count(M > B[80])
__device__ int g_fine[WNB];              // fine histogram: count(u == 81+j)
__device__ unsigned g_bin[NPIX/4];       // per-pixel exact ladder index (sat 255), 4x u8

__device__ __forceinline__ double wscale() {
  const float W = (float)(1.0 / 25.0);
  return (double)W / 8388608.0;
}

// ---------------------------------------------------------------------------
// K0a: exact integer boundaries, parallel over 8 blocks (fp64 is per-SM slow).
// ---------------------------------------------------------------------------
__global__ void __launch_bounds__(128) k_bound() {
  const int k = blockIdx.x * 128 + threadIdx.x;   // grid 8 x 128 = 1024
  if (blockIdx.x == 0) {
    if (threadIdx.x == 0) g_cnt80 = 0;
    if (threadIdx.x < WNB) g_fine[threadIdx.x] = 0;
  }
  float T = 0.5f;                                  // exact fp32 ladder replay
  for (int i = 0; i < k; ++i) T = T - 0.0005f;
  const double c = wscale();
  double dM = (double)T / c;
  long long Mg = (long long)floor(dM);
  if (Mg < -1) Mg = -1;
  if (Mg > 400000000LL) Mg = 400000000LL;
  while ((float)((double)(Mg + 1) * c) <= T) Mg++;
  while (Mg >= 0 && (float)((double)Mg * c) > T) Mg--;
  g_B[k] = (int)Mg;
}

// ---------------------------------------------------------------------------
// K0b: LUT cells via binary search over B (smem copy). Grid 8 x 1024.
// ---------------------------------------------------------------------------
__global__ void __launch_bounds__(1024) k_lut() {
  __shared__ int Bsh[NT];
  const int t = threadIdx.x;
  Bsh[t] = g_B[t];
  __syncthreads();
  const int i = blockIdx.x * 1024 + t;
  const int B0 = Bsh[0];
  const int Mh = B0 - (i << 12);
  int lo = 1, hi = 1023, res = 1024;
  while (lo <= hi) {
    int mid = (lo + hi) >> 1;
    if (Mh > Bsh[mid]) { res = mid; hi = mid - 1; }
    else lo = mid + 1;
  }
  g_lut[i] = (unsigned char)(res > 255 ? 255 : res);
}

// ---------------------------------------------------------------------------
// K1: exact integer 5x5 box blur (running sums) + LUT-exact ladder index,
//     u8 store, register cnt80, fused per-warp fine histogram.
//     8 warps = 8 x 128-col strips; 16-row band. Grid 2048 (wave balance).
// ---------------------------------------------------------------------------
__global__ void __launch_bounds__(256) k_blur(const float* __restrict__ x) {
  __shared__ int Bsh[256];
  __shared__ unsigned char lutsh[NCELL];
  __shared__ int fh[8][WNB];
  const int tid = threadIdx.x, lane = tid & 31, w = tid >> 5;
  if (tid < 256) Bsh[tid] = g_B[tid];
  {
    const uint4* src = (const uint4*)g_lut;
    uint4* dst = (uint4*)lutsh;
    for (int i = tid; i < NCELL / 16; i += 256) dst[i] = src[i];
  }
  if (lane < 32) { fh[w][lane] = 0; fh[w][lane + 32] = 0; }
  __syncthreads();

  const int ch = blockIdx.x >> 6;                // 32 channels x 64 bands
  const int y0 = (blockIdx.x & 63) << 4;         // 16-row band
  const float4* xo = (const float4*)x + ((size_t)ch << 18);
  const float*  xs = x + ((size_t)ch << 20);
  unsigned* bp = g_bin + ((size_t)ch << 18);

  const int c0 = (w << 7) + (lane << 2);
  const int hcol = (lane == 0) ? (c0 - 2) : (c0 + 4);
  const bool hval = (lane == 0) ? (w > 0) : ((lane == 31) && (w < 7));
  const int B0 = Bsh[0];
  int cnt80 = 0;

  auto ldOwn = [&](int y) -> int4 {
    int4 m = make_int4(0, 0, 0, 0);
    if ((unsigned)y < 1024u) {
      float4 v = __ldg(xo + ((size_t)y << 8) + tid);
      m.x = (int)(v.x * 8388608.0f);
      m.y = (int)(v.y * 8388608.0f);
      m.z = (int)(v.z * 8388608.0f);
      m.w = (int)(v.w * 8388608.0f);
    }
    return m;
  };
  auto ldHalo = [&](int y) -> int2 {
    int2 m = make_int2(0, 0);
    if (hval && (unsigned)y < 1024u) {
      float2 v = __ldg((const float2*)(xs + ((size_t)y << 10) + hcol));
      m.x = (int)(v.x * 8388608.0f);
      m.y = (int)(v.y * 8388608.0f);
    }
    return m;
  };
  auto uidx = [&](int M) -> int {
    const int d = B0 - M;
    int dc = d < 0 ? 0 : d;
    unsigned idx = (unsigned)dc >> 12;
    if (idx > NCELL - 1) idx = NCELL - 1;
    int kb = lutsh[idx];
    int k = kb + (M <= Bsh[kb]);
    if (k > 255) k = 255;
    return d < 0 ? 0 : k;
  };
  auto tally = [&](int u) {
    cnt80 += (u <= WLO);
    unsigned tb = (unsigned)(u - (WLO + 1));
    if (tb < (unsigned)WNB) atomicAdd(&fh[w][tb], 1);
  };

  int4 r0 = ldOwn(y0 - 2), r1 = ldOwn(y0 - 1), r2 = ldOwn(y0), r3 = ldOwn(y0 + 1);
  int2 h0 = ldHalo(y0 - 2), h1 = ldHalo(y0 - 1), h2 = ldHalo(y0), h3 = ldHalo(y0 + 1);
  int4 S;
  S.x = r0.x + r1.x + r2.x + r3.x;
  S.y = r0.y + r1.y + r2.y + r3.y;
  S.z = r0.z + r1.z + r2.z + r3.z;
  S.w = r0.w + r1.w + r2.w + r3.w;
  int2 Sh = make_int2(h0.x + h1.x + h2.x + h3.x, h0.y + h1.y + h2.y + h3.y);

  for (int yy = 0; yy < 16; ++yy) {
    const int y = y0 + yy;
    int4 nw = ldOwn(y + 2);
    int2 nh = ldHalo(y + 2);
    S.x += nw.x; S.y += nw.y; S.z += nw.z; S.w += nw.w;
    Sh.x += nh.x; Sh.y += nh.y;

    int l2 = __shfl_up_sync(0xFFFFFFFFu, S.z, 1);
    int l1 = __shfl_up_sync(0xFFFFFFFFu, S.w, 1);
    int q1 = __shfl_down_sync(0xFFFFFFFFu, S.x, 1);
    int q2 = __shfl_down_sync(0xFFFFFFFFu, S.y, 1);
    if (lane == 0)  { l2 = Sh.x; l1 = Sh.y; }
    if (lane == 31) { q1 = Sh.x; q2 = Sh.y; }

    const int Mx = l2 + l1 + S.x + S.y + S.z;
    const int My = Mx - l2 + S.w;
    const int Mz = My - l1 + q1;
    const int Mw = Mz - S.x + q2;

    const int u0 = uidx(Mx), u1 = uidx(My), u2 = uidx(Mz), u3 = uidx(Mw);
    bp[((size_t)y << 8) + tid] =
        (unsigned)u0 | ((unsigned)u1 << 8) | ((unsigned)u2 << 16) | ((unsigned)u3 << 24);
    tally(u0); tally(u1); tally(u2); tally(u3);

    S.x -= r0.x; S.y -= r0.y; S.z -= r0.z; S.w -= r0.w;
    Sh.x -= h0.x; Sh.y -= h0.y;
    r0 = r1; r1 = r2; r2 = r3; r3 = nw;
    h0 = h1; h1 = h2; h2 = h3; h3 = nh;
  }

  cnt80 += __shfl_down_sync(0xFFFFFFFFu, cnt80, 16);
  cnt80 += __shfl_down_sync(0xFFFFFFFFu, cnt80, 8);
  cnt80 += __shfl_down_sync(0xFFFFFFFFu, cnt80, 4);
  cnt80 += __shfl_down_sync(0xFFFFFFFFu, cnt80, 2);
  cnt80 += __shfl_down_sync(0xFFFFFFFFu, cnt80, 1);
  if (lane == 0) atomicAdd(&g_cnt80, cnt80);

  __syncthreads();
  if (tid < WNB) {
    int s = fh[0][tid] + fh[1][tid] + fh[2][tid] + fh[3][tid]
          + fh[4][tid] + fh[5][tid] + fh[6][tid] + fh[7][tid];
    if (s) atomicAdd(&g_fine[tid], s);
  }
}

// ---------------------------------------------------------------------------
// K2: fused pick (staged parallel loads) + threshold + bitwise close + expand.
// 1024x32 tiles, grid 1024.  (R13 config, frozen.)
// ---------------------------------------------------------------------------
__global__ void __launch_bounds__(256) k_morph(float* __restrict__ out) {
  __shared__ unsigned bits[40][33];
  __shared__ unsigned hd[40][33];
  __shared__ unsigned dv[36][33];
  __shared__ unsigned he[36][33];
  __shared__ unsigned ve[32][33];
  __shared__ uint4 lut16[16];
  __shared__ int sf[WNB];
  __shared__ int c80_s, a_s;
  const int tid  = threadIdx.x;
  const int lane = tid & 31;
  const int wid  = tid >> 5;
  const int ch = blockIdx.x >> 5;
  const int y0 = (blockIdx.x & 31) << 5;
  const unsigned* bw = g_bin + ((size_t)ch << 18);

  if (tid < WNB) sf[tid] = g_fine[tid];
  if (tid == WNB) c80_s = g_cnt80;
  if (tid < 16)
    lut16[tid] = make_uint4((tid & 1) ? 0x3f800000u : 0u,
                            (tid & 2) ? 0x3f800000u : 0u,
                            (tid & 4) ? 0x3f800000u : 0u,
                            (tid & 8) ? 0x3f800000u : 0u);
  __syncthreads();
  if (tid == 0) {
    const float invN = 1.0f / 33554432.0f;    // N = 2^25
    int flag = 0, a = 0;
    int C = c80_s;                            // cum count at k = 80
    if ((float)C * invN >= 0.84f) flag = 1;
    else {
      int k = -1;
      for (int j = 0; j < WNB; ++j) {
        C += sf[j];
        if ((float)C * invN >= 0.84f) { k = WLO + 1 + j; break; }
      }
      if (k < 0) flag = 1;
      else {
        while ((float)C * invN > 0.86f) {     // statistically never iterates
          if (k <= WLO) { flag = 1; break; }
          C -= sf[k - (WLO + 1)];
          k--;
        }
        a = k;
      }
    }
    if (flag) {
      // fallback (never taken): exact serial recount from stored u8 bins
      int h[256];
      for (int i = 0; i < 256; ++i) h[i] = 0;
      const unsigned char* p = (const unsigned char*)g_bin;
      for (long long i = 0; i < (long long)NPIX; ++i) h[p[i]]++;
      int C2 = 0, k = 254;
      for (int j = 0; j <= 254; ++j) {
        C2 += h[j];
        if ((float)C2 * invN >= 0.84f) { k = j; break; }
      }
      while (k > 0 && (float)C2 * invN > 0.86f) { C2 -= h[k]; k--; }
      a = k;
    }
    a_s = a;
  }
  __syncthreads();
  const int a = a_s;
  const unsigned C7 = (unsigned)(127 - (a & 127)) * 0x01010101u;
  const bool alow = a < 128;

  auto nib = [&](unsigned pk) -> unsigned {
    const unsigned hi = pk & 0x80808080u;
    const unsigned m  = ((pk & 0x7F7F7F7Fu) + C7) & 0x80808080u;
    const unsigned gt = alow ? (hi | m) : (hi & m);
    const unsigned vb = ((~gt) >> 7) & 0x01010101u;
    return (vb * 0x01020408u) >> 24;
  };

  // phase 1: threshold bitmasks; lane loads 16 px (uint4), pairs via 1 shfl
  {
    const uint4* bw4 = (const uint4*)bw;
    for (int t = wid; t < 80; t += 8) {
      const int r = t >> 1, h = t & 1;
      const int gy = y0 - 4 + r;
      unsigned v = 0;
      if ((unsigned)gy < 1024u) {
        const uint4 p4 = __ldg(&bw4[((size_t)gy << 6) + (h << 5) + lane]);
        const unsigned b16 = nib(p4.x) | (nib(p4.y) << 4)
                           | (nib(p4.z) << 8) | (nib(p4.w) << 12);
        v = b16 << ((lane & 1) << 4);
      }
      v |= __shfl_xor_sync(0xFFFFFFFFu, v, 1);
      if ((lane & 1) == 0) bits[r][(h << 4) + (lane >> 1)] = v;
    }
  }
  __syncthreads();

  // phase 2: horizontal dilate (0-fill)
  for (int idx = tid; idx < 40 * 32; idx += 256) {
    const int r = idx >> 5, w = idx & 31;
    const unsigned u = bits[r][w];
    const unsigned L = w ? bits[r][w - 1] : 0u;
    const unsigned R = (w < 31) ? bits[r][w + 1] : 0u;
    hd[r][w] = u | __funnelshift_r(u, R, 1) | __funnelshift_r(u, R, 2)
                 | __funnelshift_l(L, u, 1) | __funnelshift_l(L, u, 2);
  }
  __syncthreads();

  // phase 3: vertical dilate, sliding 5-tap window
  {
    const int w = tid & 31, g = tid >> 5;
    const int r0 = g * 5;
    if (r0 < 36) {
      const int rend = (r0 + 5 < 36) ? (r0 + 5) : 36;
      unsigned w0 = hd[r0][w],     w1 = hd[r0 + 1][w];
      unsigned w2 = hd[r0 + 2][w], w3 = hd[r0 + 3][w];
      for (int r = r0; r < rend; ++r) {
        const unsigned w4 = hd[r + 4][w];
        dv[r][w] = w0 | w1 | w2 | w3 | w4;
        w0 = w1; w1 = w2; w2 = w3; w3 = w4;
      }
    }
  }
  __syncthreads();

  // phase 4: horizontal erode (1-fill); out-of-image rows forced to all-ones
  for (int idx = tid; idx < 36 * 32; idx += 256) {
    const int r = idx >> 5, w = idx & 31;
    const unsigned u = dv[r][w];
    const unsigned L = w ? dv[r][w - 1] : 0xFFFFFFFFu;
    const unsigned R = (w < 31) ? dv[r][w + 1] : 0xFFFFFFFFu;
    unsigned res = u & __funnelshift_r(u, R, 1) & __funnelshift_r(u, R, 2)
                     & __funnelshift_l(L, u, 1) & __funnelshift_l(L, u, 2);
    if ((y0 == 0 && r < 2) || (y0 == 992 && r >= 34)) res = 0xFFFFFFFFu;
    he[r][w] = res;
  }
  __syncthreads();

  // phase 5a: vertical erode, sliding 5-tap window (clip-free)
  {
    const int w = tid & 31, g = tid >> 5;
    const int r0 = g << 2;
    unsigned w0 = he[r0][w],     w1 = he[r0 + 1][w];
    unsigned w2 = he[r0 + 2][w], w3 = he[r0 + 3][w];
#pragma unroll
    for (int i = 0; i < 4; ++i) {
      const unsigned w4 = he[r0 + 4 + i][w];
      ve[r0 + i][w] = w0 & w1 & w2 & w3 & w4;
      w0 = w1; w1 = w2; w2 = w3; w3 = w4;
    }
  }
  __syncthreads();

  // phase 5b: LUT16 expand + coalesced uint4 stores
  uint4* op = (uint4*)out + ((size_t)ch << 18);
  for (int task = wid; task < 32 * 8; task += 8) {
    const int yy = task >> 3, seg = task & 7;
    const int gy = y0 + yy;
    const unsigned o = ve[yy][(seg << 2) + (lane >> 3)];
    op[((size_t)gy << 8) + (seg << 5) + lane] = lut16[(o >> ((lane & 7) << 2)) & 15u];
  }
}

// ---------------------------------------------------------------------------
extern "C" void kernel_launch(void* const* d_in, const int* in_sizes, int n_in,
                              void* d_out, int out_size) {
  const float* x = (const float*)d_in[0];
  if (n_in > 1 && in_sizes[0] < in_sizes[1]) x = (const float*)d_in[1];

  k_bound<<<8,    128 >>>();
  k_lut  <<<8,    1024>>>();
  k_blur <<<2048, 256 >>>(x);
  k_morph<<<1024, 256 >>>((float*)d_out);
}

// round 16
// speedup vs baseline: 1.0530x; 1.0172x over previous
#include <cuda_runtime.h>
#include <cstdint>
#include <math.h>

#define NPIX  (8*4*1024*1024)
#define NCELL 8192
#define WLO   80          // fine window covers k in [81, 144]
#define WNB   64

// ---- host-computed tables, passed as kernel param (capture-time, free) ----
struct __align__(16) Tables {
  int B[256];                                   // integer boundaries
  __align__(16) unsigned char lut[NCELL];       // cell -> kb (sat 255)
};

// ---- static device scratch ----
__device__ int g_B[256];
__device__ __align__(16) unsigned char g_lut[NCELL];
__device__ int g_cnt80;
__device__ int g_fine[WNB];
__device__ unsigned g_bin[NPIX/4];   // per-pixel exact ladder index (sat 255), 4x u8

// ---------------------------------------------------------------------------
// K0: upload host-computed tables, zero counters. One block.
// ---------------------------------------------------------------------------
__global__ void __launch_bounds__(1024) k_tab(const __grid_constant__ Tables tbl) {
  const int t = threadIdx.x;
  if (t < 256) g_B[t] = tbl.B[t];
  if (t < NCELL / 16)
    ((uint4*)g_lut)[t] = ((const uint4*)tbl.lut)[t];
  else if (t >= 512 && t < 512 + NCELL / 16)
    ((uint4*)g_lut)[t - 512 + NCELL / 16] = ((const uint4*)tbl.lut)[t - 512 + NCELL / 16];
  if (t == 1023) g_cnt80 = 0;
  if (t >= 768 && t < 768 + WNB) g_fine[t - 768] = 0;
}

// ---------------------------------------------------------------------------
// K1: exact integer 5x5 box blur (running sums) + LUT-exact ladder index,
//     u8 store, register cnt80, fused per-warp fine histogram.
//     8 warps = 8 x 128-col strips; 32-row band. Grid 1024.  (R13, frozen)
// ---------------------------------------------------------------------------
__global__ void __launch_bounds__(256) k_blur(const float* __restrict__ x) {
  __shared__ int Bsh[256];
  __shared__ unsigned char lutsh[NCELL];
  __shared__ int fh[8][WNB];
  const int tid = threadIdx.x, lane = tid & 31, w = tid >> 5;
  if (tid < 256) Bsh[tid] = g_B[tid];
  {
    const uint4* src = (const uint4*)g_lut;
    uint4* dst = (uint4*)lutsh;
    for (int i = tid; i < NCELL / 16; i += 256) dst[i] = src[i];
  }
  if (lane < 32) { fh[w][lane] = 0; fh[w][lane + 32] = 0; }
  __syncthreads();

  const int ch = blockIdx.x >> 5;
  const int y0 = (blockIdx.x & 31) << 5;
  const float4* xo = (const float4*)x + ((size_t)ch << 18);
  const float*  xs = x + ((size_t)ch << 20);
  unsigned* bp = g_bin + ((size_t)ch << 18);

  const int c0 = (w << 7) + (lane << 2);
  const int hcol = (lane == 0) ? (c0 - 2) : (c0 + 4);
  const bool hval = (lane == 0) ? (w > 0) : ((lane == 31) && (w < 7));
  const int B0 = Bsh[0];
  int cnt80 = 0;

  auto ldOwn = [&](int y) -> int4 {
    int4 m = make_int4(0, 0, 0, 0);
    if ((unsigned)y < 1024u) {
      float4 v = __ldg(xo + ((size_t)y << 8) + tid);
      m.x = (int)(v.x * 8388608.0f);
      m.y = (int)(v.y * 8388608.0f);
      m.z = (int)(v.z * 8388608.0f);
      m.w = (int)(v.w * 8388608.0f);
    }
    return m;
  };
  auto ldHalo = [&](int y) -> int2 {
    int2 m = make_int2(0, 0);
    if (hval && (unsigned)y < 1024u) {
      float2 v = __ldg((const float2*)(xs + ((size_t)y << 10) + hcol));
      m.x = (int)(v.x * 8388608.0f);
      m.y = (int)(v.y * 8388608.0f);
    }
    return m;
  };
  auto uidx = [&](int M) -> int {
    const int d = B0 - M;
    int dc = d < 0 ? 0 : d;
    unsigned idx = (unsigned)dc >> 12;
    if (idx > NCELL - 1) idx = NCELL - 1;
    int kb = lutsh[idx];
    int k = kb + (M <= Bsh[kb]);
    if (k > 255) k = 255;
    return d < 0 ? 0 : k;
  };
  auto tally = [&](int u) {
    cnt80 += (u <= WLO);
    unsigned tb = (unsigned)(u - (WLO + 1));
    if (tb < (unsigned)WNB) atomicAdd(&fh[w][tb], 1);
  };

  int4 r0 = ldOwn(y0 - 2), r1 = ldOwn(y0 - 1), r2 = ldOwn(y0), r3 = ldOwn(y0 + 1);
  int2 h0 = ldHalo(y0 - 2), h1 = ldHalo(y0 - 1), h2 = ldHalo(y0), h3 = ldHalo(y0 + 1);
  int4 S;
  S.x = r0.x + r1.x + r2.x + r3.x;
  S.y = r0.y + r1.y + r2.y + r3.y;
  S.z = r0.z + r1.z + r2.z + r3.z;
  S.w = r0.w + r1.w + r2.w + r3.w;
  int2 Sh = make_int2(h0.x + h1.x + h2.x + h3.x, h0.y + h1.y + h2.y + h3.y);

  for (int yy = 0; yy < 32; ++yy) {
    const int y = y0 + yy;
    int4 nw = ldOwn(y + 2);
    int2 nh = ldHalo(y + 2);
    S.x += nw.x; S.y += nw.y; S.z += nw.z; S.w += nw.w;
    Sh.x += nh.x; Sh.y += nh.y;

    int l2 = __shfl_up_sync(0xFFFFFFFFu, S.z, 1);
    int l1 = __shfl_up_sync(0xFFFFFFFFu, S.w, 1);
    int q1 = __shfl_down_sync(0xFFFFFFFFu, S.x, 1);
    int q2 = __shfl_down_sync(0xFFFFFFFFu, S.y, 1);
    if (lane == 0)  { l2 = Sh.x; l1 = Sh.y; }
    if (lane == 31) { q1 = Sh.x; q2 = Sh.y; }

    const int Mx = l2 + l1 + S.x + S.y + S.z;
    const int My = Mx - l2 + S.w;
    const int Mz = My - l1 + q1;
    const int Mw = Mz - S.x + q2;

    const int u0 = uidx(Mx), u1 = uidx(My), u2 = uidx(Mz), u3 = uidx(Mw);
    bp[((size_t)y << 8) + tid] =
        (unsigned)u0 | ((unsigned)u1 << 8) | ((unsigned)u2 << 16) | ((unsigned)u3 << 24);
    tally(u0); tally(u1); tally(u2); tally(u3);

    S.x -= r0.x; S.y -= r0.y; S.z -= r0.z; S.w -= r0.w;
    Sh.x -= h0.x; Sh.y -= h0.y;
    r0 = r1; r1 = r2; r2 = r3; r3 = nw;
    h0 = h1; h1 = h2; h2 = h3; h3 = nh;
  }

  cnt80 += __shfl_down_sync(0xFFFFFFFFu, cnt80, 16);
  cnt80 += __shfl_down_sync(0xFFFFFFFFu, cnt80, 8);
  cnt80 += __shfl_down_sync(0xFFFFFFFFu, cnt80, 4);
  cnt80 += __shfl_down_sync(0xFFFFFFFFu, cnt80, 2);
  cnt80 += __shfl_down_sync(0xFFFFFFFFu, cnt80, 1);
  if (lane == 0) atomicAdd(&g_cnt80, cnt80);

  __syncthreads();
  if (tid < WNB) {
    int s = fh[0][tid] + fh[1][tid] + fh[2][tid] + fh[3][tid]
          + fh[4][tid] + fh[5][tid] + fh[6][tid] + fh[7][tid];
    if (s) atomicAdd(&g_fine[tid], s);
  }
}

// ---------------------------------------------------------------------------
// K2: fused pick (staged parallel loads) + threshold + bitwise close + expand.
// 1024x32 tiles, grid 1024.  (R13 config, frozen.)
// ---------------------------------------------------------------------------
__global__ void __launch_bounds__(256) k_morph(float* __restrict__ out) {
  __shared__ unsigned bits[40][33];
  __shared__ unsigned hd[40][33];
  __shared__ unsigned dv[36][33];
  __shared__ unsigned he[36][33];
  __shared__ unsigned ve[32][33];
  __shared__ uint4 lut16[16];
  __shared__ int sf[WNB];
  __shared__ int c80_s, a_s;
  const int tid  = threadIdx.x;
  const int lane = tid & 31;
  const int wid  = tid >> 5;
  const int ch = blockIdx.x >> 5;
  const int y0 = (blockIdx.x & 31) << 5;
  const unsigned* bw = g_bin + ((size_t)ch << 18);

  if (tid < WNB) sf[tid] = g_fine[tid];
  if (tid == WNB) c80_s = g_cnt80;
  if (tid < 16)
    lut16[tid] = make_uint4((tid & 1) ? 0x3f800000u : 0u,
                            (tid & 2) ? 0x3f800000u : 0u,
                            (tid & 4) ? 0x3f800000u : 0u,
                            (tid & 8) ? 0x3f800000u : 0u);
  __syncthreads();
  if (tid == 0) {
    const float invN = 1.0f / 33554432.0f;    // N = 2^25
    int flag = 0, a = 0;
    int C = c80_s;                            // cum count at k = 80
    if ((float)C * invN >= 0.84f) flag = 1;
    else {
      int k = -1;
      for (int j = 0; j < WNB; ++j) {
        C += sf[j];
        if ((float)C * invN >= 0.84f) { k = WLO + 1 + j; break; }
      }
      if (k < 0) flag = 1;
      else {
        while ((float)C * invN > 0.86f) {     // statistically never iterates
          if (k <= WLO) { flag = 1; break; }
          C -= sf[k - (WLO + 1)];
          k--;
        }
        a = k;
      }
    }
    if (flag) {
      // fallback (never taken): exact serial recount from stored u8 bins
      int h[256];
      for (int i = 0; i < 256; ++i) h[i] = 0;
      const unsigned char* p = (const unsigned char*)g_bin;
      for (long long i = 0; i < (long long)NPIX; ++i) h[p[i]]++;
      int C2 = 0, k = 254;
      for (int j = 0; j <= 254; ++j) {
        C2 += h[j];
        if ((float)C2 * invN >= 0.84f) { k = j; break; }
      }
      while (k > 0 && (float)C2 * invN > 0.86f) { C2 -= h[k]; k--; }
      a = k;
    }
    a_s = a;
  }
  __syncthreads();
  const int a = a_s;
  const unsigned C7 = (unsigned)(127 - (a & 127)) * 0x01010101u;
  const bool alow = a < 128;

  auto nib = [&](unsigned pk) -> unsigned {
    const unsigned hi = pk & 0x80808080u;
    const unsigned m  = ((pk & 0x7F7F7F7Fu) + C7) & 0x80808080u;
    const unsigned gt = alow ? (hi | m) : (hi & m);
    const unsigned vb = ((~gt) >> 7) & 0x01010101u;
    return (vb * 0x01020408u) >> 24;
  };

  // phase 1: threshold bitmasks; lane loads 16 px (uint4), pairs via 1 shfl
  {
    const uint4* bw4 = (const uint4*)bw;
    for (int t = wid; t < 80; t += 8) {
      const int r = t >> 1, h = t & 1;
      const int gy = y0 - 4 + r;
      unsigned v = 0;
      if ((unsigned)gy < 1024u) {
        const uint4 p4 = __ldg(&bw4[((size_t)gy << 6) + (h << 5) + lane]);
        const unsigned b16 = nib(p4.x) | (nib(p4.y) << 4)
                           | (nib(p4.z) << 8) | (nib(p4.w) << 12);
        v = b16 << ((lane & 1) << 4);
      }
      v |= __shfl_xor_sync(0xFFFFFFFFu, v, 1);
      if ((lane & 1) == 0) bits[r][(h << 4) + (lane >> 1)] = v;
    }
  }
  __syncthreads();

  // phase 2: horizontal dilate (0-fill)
  for (int idx = tid; idx < 40 * 32; idx += 256) {
    const int r = idx >> 5, w = idx & 31;
    const unsigned u = bits[r][w];
    const unsigned L = w ? bits[r][w - 1] : 0u;
    const unsigned R = (w < 31) ? bits[r][w + 1] : 0u;
    hd[r][w] = u | __funnelshift_r(u, R, 1) | __funnelshift_r(u, R, 2)
                 | __funnelshift_l(L, u, 1) | __funnelshift_l(L, u, 2);
  }
  __syncthreads();

  // phase 3: vertical dilate, sliding 5-tap window
  {
    const int w = tid & 31, g = tid >> 5;
    const int r0 = g * 5;
    if (r0 < 36) {
      const int rend = (r0 + 5 < 36) ? (r0 + 5) : 36;
      unsigned w0 = hd[r0][w],     w1 = hd[r0 + 1][w];
      unsigned w2 = hd[r0 + 2][w], w3 = hd[r0 + 3][w];
      for (int r = r0; r < rend; ++r) {
        const unsigned w4 = hd[r + 4][w];
        dv[r][w] = w0 | w1 | w2 | w3 | w4;
        w0 = w1; w1 = w2; w2 = w3; w3 = w4;
      }
    }
  }
  __syncthreads();

  // phase 4: horizontal erode (1-fill); out-of-image rows forced to all-ones
  for (int idx = tid; idx < 36 * 32; idx += 256) {
    const int r = idx >> 5, w = idx & 31;
    const unsigned u = dv[r][w];
    const unsigned L = w ? dv[r][w - 1] : 0xFFFFFFFFu;
    const unsigned R = (w < 31) ? dv[r][w + 1] : 0xFFFFFFFFu;
    unsigned res = u & __funnelshift_r(u, R, 1) & __funnelshift_r(u, R, 2)
                     & __funnelshift_l(L, u, 1) & __funnelshift_l(L, u, 2);
    if ((y0 == 0 && r < 2) || (y0 == 992 && r >= 34)) res = 0xFFFFFFFFu;
    he[r][w] = res;
  }
  __syncthreads();

  // phase 5a: vertical erode, sliding 5-tap window (clip-free)
  {
    const int w = tid & 31, g = tid >> 5;
    const int r0 = g << 2;
    unsigned w0 = he[r0][w],     w1 = he[r0 + 1][w];
    unsigned w2 = he[r0 + 2][w], w3 = he[r0 + 3][w];
#pragma unroll
    for (int i = 0; i < 4; ++i) {
      const unsigned w4 = he[r0 + 4 + i][w];
      ve[r0 + i][w] = w0 & w1 & w2 & w3 & w4;
      w0 = w1; w1 = w2; w2 = w3; w3 = w4;
    }
  }
  __syncthreads();

  // phase 5b: LUT16 expand + coalesced uint4 stores
  uint4* op = (uint4*)out + ((size_t)ch << 18);
  for (int task = wid; task < 32 * 8; task += 8) {
    const int yy = task >> 3, seg = task & 7;
    const int gy = y0 + yy;
    const unsigned o = ve[yy][(seg << 2) + (lane >> 3)];
    op[((size_t)gy << 8) + (seg << 5) + lane] = lut16[(o >> ((lane & 7) << 2)) & 15u];
  }
}

// ---------------------------------------------------------------------------
// Host: compute exact tables at graph-capture time (free during replay).
// ---------------------------------------------------------------------------
static void host_tables(Tables& tb) {
  static double c = 0.0;
  c = (double)((float)(1.0 / 25.0)) / 8388608.0;
  // fp32 ladder (exact replay of t -= 0.0005f) and fp64 boundary search
  float t = 0.5f;
  float T[1024];
  for (int k = 0; k < 1024; ++k) { T[k] = t; t = t - 0.0005f; }
  int B[1024];
  for (int k = 0; k < 1024; ++k) {
    double dM = (double)T[k] / c;
    long long Mg = (long long)floor(dM);
    if (Mg < -1) Mg = -1;
    if (Mg > 400000000LL) Mg = 400000000LL;
    while ((float)((double)(Mg + 1) * c) <= T[k]) Mg++;
    while (Mg >= 0 && (float)((double)Mg * c) > T[k]) Mg--;
    B[k] = (int)Mg;
  }
  for (int k = 0; k < 256; ++k) tb.B[k] = B[k];
  const int B0 = B[0];
  for (int i = 0; i < NCELL; ++i) {
    const int Mh = B0 - (i << 12);          // largest M in cell
    int lo = 1, hi = 1023, res = 1024;      // smallest k with Mh > B[k]
    while (lo <= hi) {
      int mid = (lo + hi) >> 1;
      if (Mh > B[mid]) { res = mid; hi = mid - 1; }
      else lo = mid + 1;
    }
    tb.lut[i] = (unsigned char)(res > 255 ? 255 : res);
  }
}

extern "C" void kernel_launch(void* const* d_in, const int* in_sizes, int n_in,
                              void* d_out, int out_size) {
  const float* x = (const float*)d_in[0];
  if (n_in > 1 && in_sizes[0] < in_sizes[1]) x = (const float*)d_in[1];

  static Tables tb;
  host_tables(tb);                 // capture-time only; replay cost = 0

  k_tab  <<<1,    1024>>>(tb);
  k_blur <<<1024, 256 >>>(x);
  k_morph<<<1024, 256 >>>((float*)d_out);
}

// round 17
// speedup vs baseline: 1.0792x; 1.0249x over previous
#include <cuda_runtime.h>
#include <cstdint>
#include <math.h>

#define NPIX  (8*4*1024*1024)
#define NCELL 8192
#define WLO   80          // fine window covers k in [81, 144]
#define WNB   64

// ---------------------------------------------------------------------------
// Compile-time exact tables.
// fp32 ladder t -= 0.0005f emulated exactly: both operands are fp32 values,
// their exact difference fits in double (<= ~35 bits), single rounding to
// float == fp32 subtraction. All other math is double/integer, correctly
// rounded at compile time (IEEE constant folding).
// ---------------------------------------------------------------------------
struct TB {
  int B[256];
  unsigned char lut[NCELL];
};

constexpr TB make_tables() {
  TB tb{};
  const double c = (double)(1.0f / 25.0f) / 8388608.0;
  const double step = (double)0.0005f;
  // full 1024-entry boundary table (local), ladder in exact-fp32-via-double
  int B[1024] = {};
  double t = 0.5;                         // == (double)0.5f
  for (int k = 0; k < 1024; ++k) {
    const float Tf = (float)t;            // exact: t holds an fp32 value
    t = (double)(float)(t - step);        // exact fp32 ladder step
    const double dM = (double)Tf / c;
    long long Mg = (long long)dM;
    if ((double)Mg > dM) Mg--;            // floor for negatives
    if (Mg < -1) Mg = -1;
    if (Mg > 400000000LL) Mg = 400000000LL;
    while ((float)((double)(Mg + 1) * c) <= Tf) Mg++;
    while (Mg >= 0 && (float)((double)Mg * c) > Tf) Mg--;
    B[k] = (int)Mg;
  }
  for (int k = 0; k < 256; ++k) tb.B[k] = B[k];
  const int B0 = B[0];
  for (int i = 0; i < NCELL; ++i) {
    const int Mh = B0 - (i << 12);        // largest M in cell
    int lo = 1, hi = 1023, res = 1024;    // smallest k with Mh > B[k]
    while (lo <= hi) {
      int mid = (lo + hi) >> 1;
      if (Mh > B[mid]) { res = mid; hi = mid - 1; }
      else lo = mid + 1;
    }
    tb.lut[i] = (unsigned char)(res > 255 ? 255 : res);
  }
  return tb;
}

__device__ __align__(16) const TB d_tb = make_tables();

// ---- static device scratch (zero-initialized at load; self-resetting) ----
__device__ int g_cnt80;
__device__ int g_fine[WNB];
__device__ int g_done;
__device__ unsigned g_bin[NPIX/4];   // per-pixel exact ladder index (sat 255), 4x u8

// ---------------------------------------------------------------------------
// K1: exact integer 5x5 box blur (running sums) + LUT-exact ladder index,
//     u8 store, register cnt80, fused per-warp fine histogram.
//     8 warps = 8 x 128-col strips; 32-row band. Grid 1024.  (frozen)
// ---------------------------------------------------------------------------
__global__ void __launch_bounds__(256) k_blur(const float* __restrict__ x) {
  __shared__ int Bsh[256];
  __shared__ unsigned char lutsh[NCELL];
  __shared__ int fh[8][WNB];
  const int tid = threadIdx.x, lane = tid & 31, w = tid >> 5;
  if (tid < 256) Bsh[tid] = d_tb.B[tid];
  {
    const uint4* src = (const uint4*)d_tb.lut;
    uint4* dst = (uint4*)lutsh;
    for (int i = tid; i < NCELL / 16; i += 256) dst[i] = __ldg(src + i);
  }
  if (lane < 32) { fh[w][lane] = 0; fh[w][lane + 32] = 0; }
  __syncthreads();

  const int ch = blockIdx.x >> 5;
  const int y0 = (blockIdx.x & 31) << 5;
  const float4* xo = (const float4*)x + ((size_t)ch << 18);
  const float*  xs = x + ((size_t)ch << 20);
  unsigned* bp = g_bin + ((size_t)ch << 18);

  const int c0 = (w << 7) + (lane << 2);
  const int hcol = (lane == 0) ? (c0 - 2) : (c0 + 4);
  const bool hval = (lane == 0) ? (w > 0) : ((lane == 31) && (w < 7));
  const int B0 = Bsh[0];
  int cnt80 = 0;

  auto ldOwn = [&](int y) -> int4 {
    int4 m = make_int4(0, 0, 0, 0);
    if ((unsigned)y < 1024u) {
      float4 v = __ldg(xo + ((size_t)y << 8) + tid);
      m.x = (int)(v.x * 8388608.0f);
      m.y = (int)(v.y * 8388608.0f);
      m.z = (int)(v.z * 8388608.0f);
      m.w = (int)(v.w * 8388608.0f);
    }
    return m;
  };
  auto ldHalo = [&](int y) -> int2 {
    int2 m = make_int2(0, 0);
    if (hval && (unsigned)y < 1024u) {
      float2 v = __ldg((const float2*)(xs + ((size_t)y << 10) + hcol));
      m.x = (int)(v.x * 8388608.0f);
      m.y = (int)(v.y * 8388608.0f);
    }
    return m;
  };
  auto uidx = [&](int M) -> int {
    const int d = B0 - M;
    int dc = d < 0 ? 0 : d;
    unsigned idx = (unsigned)dc >> 12;
    if (idx > NCELL - 1) idx = NCELL - 1;
    int kb = lutsh[idx];
    int k = kb + (M <= Bsh[kb]);
    if (k > 255) k = 255;
    return d < 0 ? 0 : k;
  };
  auto tally = [&](int u) {
    cnt80 += (u <= WLO);
    unsigned tb = (unsigned)(u - (WLO + 1));
    if (tb < (unsigned)WNB) atomicAdd(&fh[w][tb], 1);
  };

  int4 r0 = ldOwn(y0 - 2), r1 = ldOwn(y0 - 1), r2 = ldOwn(y0), r3 = ldOwn(y0 + 1);
  int2 h0 = ldHalo(y0 - 2), h1 = ldHalo(y0 - 1), h2 = ldHalo(y0), h3 = ldHalo(y0 + 1);
  int4 S;
  S.x = r0.x + r1.x + r2.x + r3.x;
  S.y = r0.y + r1.y + r2.y + r3.y;
  S.z = r0.z + r1.z + r2.z + r3.z;
  S.w = r0.w + r1.w + r2.w + r3.w;
  int2 Sh = make_int2(h0.x + h1.x + h2.x + h3.x, h0.y + h1.y + h2.y + h3.y);

  for (int yy = 0; yy < 32; ++yy) {
    const int y = y0 + yy;
    int4 nw = ldOwn(y + 2);
    int2 nh = ldHalo(y + 2);
    S.x += nw.x; S.y += nw.y; S.z += nw.z; S.w += nw.w;
    Sh.x += nh.x; Sh.y += nh.y;

    int l2 = __shfl_up_sync(0xFFFFFFFFu, S.z, 1);
    int l1 = __shfl_up_sync(0xFFFFFFFFu, S.w, 1);
    int q1 = __shfl_down_sync(0xFFFFFFFFu, S.x, 1);
    int q2 = __shfl_down_sync(0xFFFFFFFFu, S.y, 1);
    if (lane == 0)  { l2 = Sh.x; l1 = Sh.y; }
    if (lane == 31) { q1 = Sh.x; q2 = Sh.y; }

    const int Mx = l2 + l1 + S.x + S.y + S.z;
    const int My = Mx - l2 + S.w;
    const int Mz = My - l1 + q1;
    const int Mw = Mz - S.x + q2;

    const int u0 = uidx(Mx), u1 = uidx(My), u2 = uidx(Mz), u3 = uidx(Mw);
    bp[((size_t)y << 8) + tid] =
        (unsigned)u0 | ((unsigned)u1 << 8) | ((unsigned)u2 << 16) | ((unsigned)u3 << 24);
    tally(u0); tally(u1); tally(u2); tally(u3);

    S.x -= r0.x; S.y -= r0.y; S.z -= r0.z; S.w -= r0.w;
    Sh.x -= h0.x; Sh.y -= h0.y;
    r0 = r1; r1 = r2; r2 = r3; r3 = nw;
    h0 = h1; h1 = h2; h2 = h3; h3 = nh;
  }

  cnt80 += __shfl_down_sync(0xFFFFFFFFu, cnt80, 16);
  cnt80 += __shfl_down_sync(0xFFFFFFFFu, cnt80, 8);
  cnt80 += __shfl_down_sync(0xFFFFFFFFu, cnt80, 4);
  cnt80 += __shfl_down_sync(0xFFFFFFFFu, cnt80, 2);
  cnt80 += __shfl_down_sync(0xFFFFFFFFu, cnt80, 1);
  if (lane == 0) atomicAdd(&g_cnt80, cnt80);

  __syncthreads();
  if (tid < WNB) {
    int s = fh[0][tid] + fh[1][tid] + fh[2][tid] + fh[3][tid]
          + fh[4][tid] + fh[5][tid] + fh[6][tid] + fh[7][tid];
    if (s) atomicAdd(&g_fine[tid], s);
  }
}

// ---------------------------------------------------------------------------
// K2: fused pick + threshold + bitwise close + expand; counter self-reset
// via completion ticket (the 1024th block to finish staging zeroes counters).
// 1024x32 tiles, grid 1024.
// ---------------------------------------------------------------------------
__global__ void __launch_bounds__(256) k_morph(float* __restrict__ out) {
  __shared__ unsigned bits[40][33];
  __shared__ unsigned hd[40][33];
  __shared__ unsigned dv[36][33];
  __shared__ unsigned he[36][33];
  __shared__ unsigned ve[32][33];
  __shared__ uint4 lut16[16];
  __shared__ int sf[WNB];
  __shared__ int c80_s, a_s;
  const int tid  = threadIdx.x;
  const int lane = tid & 31;
  const int wid  = tid >> 5;
  const int ch = blockIdx.x >> 5;
  const int y0 = (blockIdx.x & 31) << 5;
  const unsigned* bw = g_bin + ((size_t)ch << 18);

  if (tid < WNB) sf[tid] = g_fine[tid];
  if (tid == WNB) c80_s = g_cnt80;
  if (tid < 16)
    lut16[tid] = make_uint4((tid & 1) ? 0x3f800000u : 0u,
                            (tid & 2) ? 0x3f800000u : 0u,
                            (tid & 4) ? 0x3f800000u : 0u,
                            (tid & 8) ? 0x3f800000u : 0u);
  __syncthreads();   // all counter reads of this block complete past here
  if (tid == 0) {
    const float invN = 1.0f / 33554432.0f;    // N = 2^25
    int flag = 0, a = 0;
    int C = c80_s;                            // cum count at k = 80
    if ((float)C * invN >= 0.84f) flag = 1;
    else {
      int k = -1;
      for (int j = 0; j < WNB; ++j) {
        C += sf[j];
        if ((float)C * invN >= 0.84f) { k = WLO + 1 + j; break; }
      }
      if (k < 0) flag = 1;
      else {
        while ((float)C * invN > 0.86f) {     // statistically never iterates
          if (k <= WLO) { flag = 1; break; }
          C -= sf[k - (WLO + 1)];
          k--;
        }
        a = k;
      }
    }
    if (flag) {
      // fallback (never taken): exact serial recount from stored u8 bins
      int h[256];
      for (int i = 0; i < 256; ++i) h[i] = 0;
      const unsigned char* p = (const unsigned char*)g_bin;
      for (long long i = 0; i < (long long)NPIX; ++i) h[p[i]]++;
      int C2 = 0, k = 254;
      for (int j = 0; j <= 254; ++j) {
        C2 += h[j];
        if ((float)C2 * invN >= 0.84f) { k = j; break; }
      }
      while (k > 0 && (float)C2 * invN > 0.86f) { C2 -= h[k]; k--; }
      a = k;
    }
    a_s = a;
    // completion ticket: last of 1024 blocks resets counters for next replay
    if (atomicAdd(&g_done, 1) == 1023) {
      g_cnt80 = 0;
      for (int j = 0; j < WNB; ++j) g_fine[j] = 0;
      g_done = 0;
    }
  }
  __syncthreads();
  const int a = a_s;
  const unsigned C7 = (unsigned)(127 - (a & 127)) * 0x01010101u;
  const bool alow = a < 128;

  auto nib = [&](unsigned pk) -> unsigned {
    const unsigned hi = pk & 0x80808080u;
    const unsigned m  = ((pk & 0x7F7F7F7Fu) + C7) & 0x80808080u;
    const unsigned gt = alow ? (hi | m) : (hi & m);
    const unsigned vb = ((~gt) >> 7) & 0x01010101u;
    return (vb * 0x01020408u) >> 24;
  };

  // phase 1: threshold bitmasks; lane loads 16 px (uint4), pairs via 1 shfl
  {
    const uint4* bw4 = (const uint4*)bw;
    for (int t = wid; t < 80; t += 8) {
      const int r = t >> 1, h = t & 1;
      const int gy = y0 - 4 + r;
      unsigned v = 0;
      if ((unsigned)gy < 1024u) {
        const uint4 p4 = __ldg(&bw4[((size_t)gy << 6) + (h << 5) + lane]);
        const unsigned b16 = nib(p4.x) | (nib(p4.y) << 4)
                           | (nib(p4.z) << 8) | (nib(p4.w) << 12);
        v = b16 << ((lane & 1) << 4);
      }
      v |= __shfl_xor_sync(0xFFFFFFFFu, v, 1);
      if ((lane & 1) == 0) bits[r][(h << 4) + (lane >> 1)] = v;
    }
  }
  __syncthreads();

  // phase 2: horizontal dilate (0-fill)
  for (int idx = tid; idx < 40 * 32; idx += 256) {
    const int r = idx >> 5, w = idx & 31;
    const unsigned u = bits[r][w];
    const unsigned L = w ? bits[r][w - 1] : 0u;
    const unsigned R = (w < 31) ? bits[r][w + 1] : 0u;
    hd[r][w] = u | __funnelshift_r(u, R, 1) | __funnelshift_r(u, R, 2)
                 | __funnelshift_l(L, u, 1) | __funnelshift_l(L, u, 2);
  }
  __syncthreads();

  // phase 3: vertical dilate, sliding 5-tap window
  {
    const int w = tid & 31, g = tid >> 5;
    const int r0 = g * 5;
    if (r0 < 36) {
      const int rend = (r0 + 5 < 36) ? (r0 + 5) : 36;
      unsigned w0 = hd[r0][w],     w1 = hd[r0 + 1][w];
      unsigned w2 = hd[r0 + 2][w], w3 = hd[r0 + 3][w];
      for (int r = r0; r < rend; ++r) {
        const unsigned w4 = hd[r + 4][w];
        dv[r][w] = w0 | w1 | w2 | w3 | w4;
        w0 = w1; w1 = w2; w2 = w3; w3 = w4;
      }
    }
  }
  __syncthreads();

  // phase 4: horizontal erode (1-fill); out-of-image rows forced to all-ones
  for (int idx = tid; idx < 36 * 32; idx += 256) {
    const int r = idx >> 5, w = idx & 31;
    const unsigned u = dv[r][w];
    const unsigned L = w ? dv[r][w - 1] : 0xFFFFFFFFu;
    const unsigned R = (w < 31) ? dv[r][w + 1] : 0xFFFFFFFFu;
    unsigned res = u & __funnelshift_r(u, R, 1) & __funnelshift_r(u, R, 2)
                     & __funnelshift_l(L, u, 1) & __funnelshift_l(L, u, 2);
    if ((y0 == 0 && r < 2) || (y0 == 992 && r >= 34)) res = 0xFFFFFFFFu;
    he[r][w] = res;
  }
  __syncthreads();

  // phase 5a: vertical erode, sliding 5-tap window (clip-free)
  {
    const int w = tid & 31, g = tid >> 5;
    const int r0 = g << 2;
    unsigned w0 = he[r0][w],     w1 = he[r0 + 1][w];
    unsigned w2 = he[r0 + 2][w], w3 = he[r0 + 3][w];
#pragma unroll
    for (int i = 0; i < 4; ++i) {
      const unsigned w4 = he[r0 + 4 + i][w];
      ve[r0 + i][w] = w0 & w1 & w2 & w3 & w4;
      w0 = w1; w1 = w2; w2 = w3; w3 = w4;
    }
  }
  __syncthreads();

  // phase 5b: LUT16 expand + coalesced uint4 stores
  uint4* op = (uint4*)out + ((size_t)ch << 18);
  for (int task = wid; task < 32 * 8; task += 8) {
    const int yy = task >> 3, seg = task & 7;
    const int gy = y0 + yy;
    const unsigned o = ve[yy][(seg << 2) + (lane >> 3)];
    op[((size_t)gy << 8) + (seg << 5) + lane] = lut16[(o >> ((lane & 7) << 2)) & 15u];
  }
}

// ---------------------------------------------------------------------------
extern "C" void kernel_launch(void* const* d_in, const int* in_sizes, int n_in,
                              void* d_out, int out_size) {
  const float* x = (const float*)d_in[0];
  if (n_in > 1 && in_sizes[0] < in_sizes[1]) x = (const float*)d_in[1];

  k_blur <<<1024, 256>>>(x);
  k_morph<<<1024, 256>>>((float*)d_out);
}